// round 10
// baseline (speedup 1.0000x reference)
#include <cuda_runtime.h>
#include <cstdint>

// Problem constants
#define NB    4
#define LL    2048
#define EE    1024
#define HID   1024
#define HEADS 16
#define DH    64
#define MROWS 8192
#define NPAIR 64
#define RBLK  16            // row-blocks in score kernel (2048/128)

// Scratch (static device globals)
__device__ float g_Q[MROWS * HID];
__device__ float g_K[MROWS * HID];
__device__ float g_V[MROWS * HID];
__device__ float g_diagE[NPAIR * LL];
__device__ float g_part[RBLK * NPAIR * LL];   // per-rowblock column partial sums
__device__ float g_diag[NPAIR * LL];          // final diagE / colsum

// ---------------------------------------------------------------------------
__device__ __forceinline__ uint32_t f2tf32(float x) {
    uint32_t r;
    asm("cvt.rna.tf32.f32 %0, %1;" : "=r"(r) : "f"(x));
    return r;
}

__device__ __forceinline__ void mma_tf32(float c[4], const uint32_t a[4], const uint32_t b[2]) {
    asm volatile(
        "mma.sync.aligned.m16n8k8.row.col.f32.tf32.tf32.f32 "
        "{%0,%1,%2,%3}, {%4,%5,%6,%7}, {%8,%9}, {%0,%1,%2,%3};\n"
        : "+f"(c[0]), "+f"(c[1]), "+f"(c[2]), "+f"(c[3])
        : "r"(a[0]), "r"(a[1]), "r"(a[2]), "r"(a[3]), "r"(b[0]), "r"(b[1]));
}

__device__ __forceinline__ float4 tf4(float4 v) {
    float4 w;
    w.x = __uint_as_float(f2tf32(v.x));
    w.y = __uint_as_float(f2tf32(v.y));
    w.z = __uint_as_float(f2tf32(v.z));
    w.w = __uint_as_float(f2tf32(v.w));
    return w;
}

// ---------------------------------------------------------------------------
// Tensor-core GEMM body: C[M,N] = (scale ? diag-scaled A : A)[M,K] @ B + bias.
// Block tile 128x128, BK=16, 8 warps (4m x 2n), warp tile 32x64.
// Double-buffered smem, one __syncthreads per k-tile, 2 CTAs/SM.
// k-pair permutation inside each mma (contraction order is free):
//   mma k-index cq   <-> smem col kb+2*cq
//   mma k-index cq+4 <-> smem col kb+2*cq+1
// A smem [m][k] stride 24 -> fragments via LDS.64 (conflict-free).
// B smem [k][n] stride 132 -> fragments from adjacent k rows (conflict-free),
// staging stays fully coalesced float4 (no scalar gathers).
// ---------------------------------------------------------------------------
#define GBM 128
#define GBN 128
#define GBK 16
#define ASTR 24
#define BSTR 132
#define ASZ (GBM * ASTR)   // 3072 floats
#define BSZ (GBK * BSTR)   // 2112 floats

__device__ __forceinline__ float scale_of(const float* scale, int row, int k) {
    int lr = row & (LL - 1);
    int n  = row >> 11;
    int h  = lr >> 7;
    int a  = ((lr & 127) << 4) | (k >> 6);
    return scale[((size_t)(n * HEADS + h)) * LL + a];
}

__device__ __forceinline__ void gemm_body(
    const float* __restrict__ A, const float* __restrict__ B,
    const float* __restrict__ bias, float* __restrict__ C,
    const float* __restrict__ scale, int N, int K, int bm, int bn)
{
    __shared__ float As[2 * ASZ];
    __shared__ float Bs[2 * BSZ];

    const int t    = threadIdx.x;
    const int lane = t & 31, wid = t >> 5;
    const int wm = wid & 3, wn = wid >> 2;
    const int r = lane >> 2, cq = lane & 3;

    float acc[2][8][4];
    #pragma unroll
    for (int mt = 0; mt < 2; mt++)
        #pragma unroll
        for (int nt = 0; nt < 8; nt++)
            #pragma unroll
            for (int j = 0; j < 4; j++) acc[mt][nt][j] = 0.f;

    // Per-thread staging coordinates: A tile 128x16 (2 float4/thread along k),
    // B tile 16x128 (2 float4/thread along n).
    int arow[2], aq[2], brow[2], bq[2];
    #pragma unroll
    for (int i = 0; i < 2; i++) {
        int idx = t + i * 256;
        arow[i] = idx >> 2;  aq[i] = idx & 3;      // A: row 0..127, kq 0..3
        brow[i] = idx >> 5;  bq[i] = idx & 31;     // B: k 0..15, nq 0..31
    }

    float4 pa[2], pb[2];

    // Stage k-tile 0 into buffer 0
    #pragma unroll
    for (int i = 0; i < 2; i++) {
        pa[i] = *reinterpret_cast<const float4*>(&A[(size_t)(bm + arow[i]) * K + aq[i] * 4]);
        pb[i] = *reinterpret_cast<const float4*>(&B[(size_t)brow[i] * N + bn + bq[i] * 4]);
    }
    #pragma unroll
    for (int i = 0; i < 2; i++) {
        float4 v = pa[i];
        if (scale) {
            float dd = scale_of(scale, bm + arow[i], aq[i] * 4);
            v.x *= dd; v.y *= dd; v.z *= dd; v.w *= dd;
        }
        *reinterpret_cast<float4*>(&As[arow[i] * ASTR + aq[i] * 4]) = tf4(v);
        *reinterpret_cast<float4*>(&Bs[brow[i] * BSTR + bq[i] * 4]) = tf4(pb[i]);
    }
    __syncthreads();

    const int KT = K / GBK;
    for (int kt = 0; kt < KT; kt++) {
        const int b = kt & 1;
        const float* Asb = &As[b * ASZ];
        const float* Bsb = &Bs[b * BSZ];
        const int k0n = (kt + 1) * GBK;

        if (kt + 1 < KT) {
            #pragma unroll
            for (int i = 0; i < 2; i++) {
                pa[i] = *reinterpret_cast<const float4*>(&A[(size_t)(bm + arow[i]) * K + k0n + aq[i] * 4]);
                pb[i] = *reinterpret_cast<const float4*>(&B[(size_t)(k0n + brow[i]) * N + bn + bq[i] * 4]);
            }
        }

        #pragma unroll
        for (int kk = 0; kk < 2; kk++) {
            const int kb = kk * 8;
            uint32_t af[2][4], bf[8][2];
            #pragma unroll
            for (int mt = 0; mt < 2; mt++) {
                int rb = wm * 32 + mt * 16;
                float2 a0 = *reinterpret_cast<const float2*>(&Asb[(rb + r) * ASTR + kb + 2 * cq]);
                float2 a1 = *reinterpret_cast<const float2*>(&Asb[(rb + 8 + r) * ASTR + kb + 2 * cq]);
                af[mt][0] = __float_as_uint(a0.x);   // k = 2cq
                af[mt][1] = __float_as_uint(a1.x);
                af[mt][2] = __float_as_uint(a0.y);   // k = 2cq+1
                af[mt][3] = __float_as_uint(a1.y);
            }
            #pragma unroll
            for (int nt = 0; nt < 8; nt++) {
                int cb = wn * 64 + nt * 8 + r;
                bf[nt][0] = __float_as_uint(Bsb[(kb + 2 * cq) * BSTR + cb]);      // k = 2cq
                bf[nt][1] = __float_as_uint(Bsb[(kb + 2 * cq + 1) * BSTR + cb]);  // k = 2cq+1
            }
            #pragma unroll
            for (int mt = 0; mt < 2; mt++)
                #pragma unroll
                for (int nt = 0; nt < 8; nt++)
                    mma_tf32(acc[mt][nt], af[mt], bf[nt]);
        }

        if (kt + 1 < KT) {
            float* Asn = &As[(1 - b) * ASZ];
            float* Bsn = &Bs[(1 - b) * BSZ];
            #pragma unroll
            for (int i = 0; i < 2; i++) {
                float4 v = pa[i];
                if (scale) {
                    float dd = scale_of(scale, bm + arow[i], k0n + aq[i] * 4);
                    v.x *= dd; v.y *= dd; v.z *= dd; v.w *= dd;
                }
                *reinterpret_cast<float4*>(&Asn[arow[i] * ASTR + aq[i] * 4]) = tf4(v);
                *reinterpret_cast<float4*>(&Bsn[brow[i] * BSTR + bq[i] * 4]) = tf4(pb[i]);
            }
        }
        __syncthreads();
    }

    // Epilogue with bias
    #pragma unroll
    for (int mt = 0; mt < 2; mt++) {
        int row0 = bm + wm * 32 + mt * 16 + r;
        #pragma unroll
        for (int nt = 0; nt < 8; nt++) {
            int col = bn + wn * 64 + nt * 8 + cq * 2;
            float b0 = bias[col], b1 = bias[col + 1];
            float2 v0 = make_float2(acc[mt][nt][0] + b0, acc[mt][nt][1] + b1);
            float2 v1 = make_float2(acc[mt][nt][2] + b0, acc[mt][nt][3] + b1);
            *reinterpret_cast<float2*>(&C[(size_t)row0 * N + col]) = v0;
            *reinterpret_cast<float2*>(&C[(size_t)(row0 + 8) * N + col]) = v1;
        }
    }
}

// Fused Q/K/V projection: blockIdx.z selects weight/bias/output.
__global__ __launch_bounds__(256, 2) void gemm_qkv(
    const float* __restrict__ X,
    const float* __restrict__ Wq, const float* __restrict__ Wk, const float* __restrict__ Wv,
    const float* __restrict__ bq, const float* __restrict__ bk, const float* __restrict__ bv,
    float* __restrict__ Q, float* __restrict__ K, float* __restrict__ V)
{
    const int z = blockIdx.z;
    const float* B    = (z == 0) ? Wq : (z == 1) ? Wk : Wv;
    const float* bias = (z == 0) ? bq : (z == 1) ? bk : bv;
    float*       C    = (z == 0) ? Q  : (z == 1) ? K  : V;
    gemm_body(X, B, bias, C, nullptr, HID, EE,
              blockIdx.y * GBM, blockIdx.x * GBN);
}

// O projection with fused diag scaling of A (=V).
__global__ __launch_bounds__(256, 2) void gemm_o(
    const float* __restrict__ V, const float* __restrict__ Wo,
    const float* __restrict__ bo, float* __restrict__ C,
    const float* __restrict__ diag)
{
    gemm_body(V, Wo, bo, C, diag, HID, HID,
              blockIdx.y * GBM, blockIdx.x * GBN);
}

// ---------------------------------------------------------------------------
// Score kernel, split over row blocks. Block (cb, rb, p):
//   S = Q[rb-tile] @ K[cb-tile]^T (128x128x64, tf32 mma), e = exp(S/1024),
//   column partial sums -> g_part[rb][p][col]; diag captured when rb==cb.
// 8 warps (4a x 2b), warp tile 32(a) x 64(b). LDS.64 fragments via k-pair perm.
// ---------------------------------------------------------------------------
#define SSTR 72

__global__ __launch_bounds__(256, 2) void score_diag_tc(
    const float* __restrict__ Q, const float* __restrict__ Km,
    float* __restrict__ diagE, float* __restrict__ partG)
{
    extern __shared__ float sm[];
    float* Ks   = sm;                   // 128 x SSTR
    float* Qs   = sm + 128 * SSTR;      // 128 x SSTR
    float* csum = sm + 2 * 128 * SSTR;  // 128

    const int t    = threadIdx.x;
    const int lane = t & 31, wid = t >> 5;
    const int wm = wid & 3, wn = wid >> 2;
    const int r = lane >> 2, cq = lane & 3;

    const int cb = blockIdx.x;          // column block 0..15
    const int rb = blockIdx.y;          // row block 0..15
    const int p  = blockIdx.z;          // pair 0..63
    const int bn = cb * 128;
    const int a0 = rb * 128;
    const float* Qh = Q  + (size_t)p * LL * DH;
    const float* Kh = Km + (size_t)p * LL * DH;

    // Load K tile (cols) and Q tile (rows), tf32-rounded
    #pragma unroll
    for (int i = 0; i < 8; i++) {
        int idx = t + i * 256;
        int row = idx >> 4, q = idx & 15;
        float4 v = *reinterpret_cast<const float4*>(&Kh[(size_t)(bn + row) * DH + q * 4]);
        *reinterpret_cast<float4*>(&Ks[row * SSTR + q * 4]) = tf4(v);
    }
    #pragma unroll
    for (int i = 0; i < 8; i++) {
        int idx = t + i * 256;
        int row = idx >> 4, q = idx & 15;
        float4 v = *reinterpret_cast<const float4*>(&Qh[(size_t)(a0 + row) * DH + q * 4]);
        *reinterpret_cast<float4*>(&Qs[row * SSTR + q * 4]) = tf4(v);
    }
    __syncthreads();

    float acc[2][8][4];
    #pragma unroll
    for (int mt = 0; mt < 2; mt++)
        #pragma unroll
        for (int nt = 0; nt < 8; nt++)
            #pragma unroll
            for (int j = 0; j < 4; j++) acc[mt][nt][j] = 0.f;

    #pragma unroll
    for (int kk = 0; kk < 8; kk++) {
        const int kb = kk * 8;
        uint32_t af[2][4], bf[8][2];
        #pragma unroll
        for (int mt = 0; mt < 2; mt++) {
            int rbm = wm * 32 + mt * 16;
            float2 a0f = *reinterpret_cast<const float2*>(&Qs[(rbm + r) * SSTR + kb + 2 * cq]);
            float2 a1f = *reinterpret_cast<const float2*>(&Qs[(rbm + 8 + r) * SSTR + kb + 2 * cq]);
            af[mt][0] = __float_as_uint(a0f.x);
            af[mt][1] = __float_as_uint(a1f.x);
            af[mt][2] = __float_as_uint(a0f.y);
            af[mt][3] = __float_as_uint(a1f.y);
        }
        #pragma unroll
        for (int nt = 0; nt < 8; nt++) {
            int cbi = wn * 64 + nt * 8 + r;
            float2 b0f = *reinterpret_cast<const float2*>(&Ks[cbi * SSTR + kb + 2 * cq]);
            bf[nt][0] = __float_as_uint(b0f.x);
            bf[nt][1] = __float_as_uint(b0f.y);
        }
        #pragma unroll
        for (int mt = 0; mt < 2; mt++)
            #pragma unroll
            for (int nt = 0; nt < 8; nt++)
                mma_tf32(acc[mt][nt], af[mt], bf[nt]);
    }

    // exp + per-warp column partials; capture diagonal when rb==cb
    const float S = 1.0f / 1024.0f;
    const bool diagblk = (rb == cb);
    float partial[8][2];
    #pragma unroll
    for (int nt = 0; nt < 8; nt++) { partial[nt][0] = 0.f; partial[nt][1] = 0.f; }

    #pragma unroll
    for (int mt = 0; mt < 2; mt++) {
        int arow0 = wm * 32 + mt * 16 + r;
        #pragma unroll
        for (int nt = 0; nt < 8; nt++) {
            #pragma unroll
            for (int j = 0; j < 2; j++) {
                int bcol = wn * 64 + nt * 8 + cq * 2 + j;
                float e0 = __expf(acc[mt][nt][j] * S);
                float e1 = __expf(acc[mt][nt][2 + j] * S);
                partial[nt][j] += e0 + e1;
                if (diagblk) {
                    if (arow0 == bcol)     diagE[(size_t)p * LL + bn + bcol] = e0;
                    if (arow0 + 8 == bcol) diagE[(size_t)p * LL + bn + bcol] = e1;
                }
            }
        }
    }

    // Reduce partials over the 8 row-groups within the warp
    #pragma unroll
    for (int nt = 0; nt < 8; nt++)
        #pragma unroll
        for (int j = 0; j < 2; j++) {
            float v = partial[nt][j];
            v += __shfl_xor_sync(0xFFFFFFFF, v, 4);
            v += __shfl_xor_sync(0xFFFFFFFF, v, 8);
            v += __shfl_xor_sync(0xFFFFFFFF, v, 16);
            partial[nt][j] = v;
        }

    if (t < 128) csum[t] = 0.f;
    __syncthreads();
    if (r == 0) {
        #pragma unroll
        for (int nt = 0; nt < 8; nt++)
            #pragma unroll
            for (int j = 0; j < 2; j++)
                atomicAdd(&csum[wn * 64 + nt * 8 + cq * 2 + j], partial[nt][j]);
    }
    __syncthreads();
    if (t < 128)
        partG[((size_t)rb * NPAIR + p) * LL + bn + t] = csum[t];
}

// ---------------------------------------------------------------------------
// diag[p][c] = diagE[p][c] / sum_rb part[rb][p][c]
// ---------------------------------------------------------------------------
__global__ __launch_bounds__(256) void divide_kernel(
    const float* __restrict__ diagE, const float* __restrict__ part,
    float* __restrict__ diag)
{
    int i = blockIdx.x * 256 + threadIdx.x;           // over NPAIR*LL
    if (i >= NPAIR * LL) return;
    float s = 0.f;
    #pragma unroll
    for (int rb = 0; rb < RBLK; rb++)
        s += part[(size_t)rb * NPAIR * LL + i];
    diag[i] = diagE[i] / s;
}

// ---------------------------------------------------------------------------
extern "C" void kernel_launch(void* const* d_in, const int* in_sizes, int n_in,
                              void* d_out, int out_size)
{
    const float* X  = (const float*)d_in[0];
    const float* Wq = (const float*)d_in[1];
    const float* bq = (const float*)d_in[2];
    const float* Wk = (const float*)d_in[3];
    const float* bk = (const float*)d_in[4];
    const float* Wv = (const float*)d_in[5];
    const float* bv = (const float*)d_in[6];
    const float* Wo = (const float*)d_in[7];
    const float* bo = (const float*)d_in[8];
    float* out = (float*)d_out;

    float *Q, *K, *V, *dgE, *pt, *dg;
    cudaGetSymbolAddress((void**)&Q,   g_Q);
    cudaGetSymbolAddress((void**)&K,   g_K);
    cudaGetSymbolAddress((void**)&V,   g_V);
    cudaGetSymbolAddress((void**)&dgE, g_diagE);
    cudaGetSymbolAddress((void**)&pt,  g_part);
    cudaGetSymbolAddress((void**)&dg,  g_diag);

    const int score_smem = (2 * 128 * SSTR + 128) * sizeof(float);
    static int attr_done = 0;
    if (!attr_done) {
        cudaFuncSetAttribute(score_diag_tc,
                             cudaFuncAttributeMaxDynamicSharedMemorySize, score_smem);
        attr_done = 1;
    }

    dim3 qkv_grid(HID / GBN, MROWS / GBM, 3);   // (8, 64, 3) = 1536 blocks
    gemm_qkv<<<qkv_grid, 256>>>(X, Wq, Wk, Wv, bq, bk, bv, Q, K, V);

    dim3 sgrid(LL / 128, RBLK, NPAIR);          // (16, 16, 64)
    score_diag_tc<<<sgrid, 256, score_smem>>>(Q, K, dgE, pt);

    divide_kernel<<<(NPAIR * LL + 255) / 256, 256>>>(dgE, pt, dg);

    dim3 ogrid(HID / GBN, MROWS / GBM);         // (8, 64)
    gemm_o<<<ogrid, 256>>>(V, Wo, bo, out, dg);
}

// round 12
// speedup vs baseline: 1.1509x; 1.1509x over previous
#include <cuda_runtime.h>
#include <cstdint>

// Problem constants
#define NB    4
#define LL    2048
#define EE    1024
#define HID   1024
#define HEADS 16
#define DH    64
#define MROWS 8192
#define NPAIR 64
#define RBG   4             // row-block groups in score kernel
#define RPG   4             // row-blocks per group (RBG*RPG*128 = 2048)

// Scratch (static device globals)
__device__ float g_Q[MROWS * HID];
__device__ float g_K[MROWS * HID];
__device__ float g_V[MROWS * HID];
__device__ float g_diagE[NPAIR * LL];
__device__ float g_part[RBG * NPAIR * LL];    // per-rowgroup column partial sums
__device__ float g_diag[NPAIR * LL];          // final diagE / colsum

// ---------------------------------------------------------------------------
__device__ __forceinline__ uint32_t f2tf32(float x) {
    uint32_t r;
    asm("cvt.rna.tf32.f32 %0, %1;" : "=r"(r) : "f"(x));
    return r;
}

__device__ __forceinline__ void mma_tf32(float c[4], const uint32_t a[4], const uint32_t b[2]) {
    asm volatile(
        "mma.sync.aligned.m16n8k8.row.col.f32.tf32.tf32.f32 "
        "{%0,%1,%2,%3}, {%4,%5,%6,%7}, {%8,%9}, {%0,%1,%2,%3};\n"
        : "+f"(c[0]), "+f"(c[1]), "+f"(c[2]), "+f"(c[3])
        : "r"(a[0]), "r"(a[1]), "r"(a[2]), "r"(a[3]), "r"(b[0]), "r"(b[1]));
}

__device__ __forceinline__ float4 tf4(float4 v) {
    float4 w;
    w.x = __uint_as_float(f2tf32(v.x));
    w.y = __uint_as_float(f2tf32(v.y));
    w.z = __uint_as_float(f2tf32(v.z));
    w.w = __uint_as_float(f2tf32(v.w));
    return w;
}

// ---------------------------------------------------------------------------
// Tensor-core GEMM body (R8 layout): C = (scale ? diag*A : A) @ B + bias.
// Block tile 128x128, BK=16, 8 warps (4m x 2n), warp tile 32x64.
// Double-buffered smem, one __syncthreads per k-tile, 2 CTAs/SM.
// ---------------------------------------------------------------------------
#define GBM 128
#define GBN 128
#define GBK 16
#define ASTR 20
#define BSTR 136
#define ASZ (GBM * ASTR)   // 2560 floats
#define BSZ (GBK * BSTR)   // 2176 floats

__device__ __forceinline__ float scale_of(const float* scale, int row, int k) {
    int lr = row & (LL - 1);
    int n  = row >> 11;
    int h  = lr >> 7;
    int a  = ((lr & 127) << 4) | (k >> 6);
    return scale[((size_t)(n * HEADS + h)) * LL + a];
}

__device__ __forceinline__ void gemm_body(
    const float* __restrict__ A, const float* __restrict__ B,
    const float* __restrict__ bias, float* __restrict__ C,
    const float* __restrict__ scale, int N, int K, int bm, int bn)
{
    __shared__ float As[2 * ASZ];
    __shared__ float Bs[2 * BSZ];

    const int t    = threadIdx.x;
    const int lane = t & 31, wid = t >> 5;
    const int wm = wid & 3, wn = wid >> 2;
    const int r = lane >> 2, cq = lane & 3;

    float acc[2][8][4];
    #pragma unroll
    for (int mt = 0; mt < 2; mt++)
        #pragma unroll
        for (int nt = 0; nt < 8; nt++)
            #pragma unroll
            for (int j = 0; j < 4; j++) acc[mt][nt][j] = 0.f;

    int arow[2], aq[2], brow[2], bq[2];
    #pragma unroll
    for (int i = 0; i < 2; i++) {
        int idx = t + i * 256;
        arow[i] = idx >> 2;  aq[i] = idx & 3;      // A: row 0..127, kq 0..3
        brow[i] = idx >> 5;  bq[i] = idx & 31;     // B: k 0..15, nq 0..31
    }

    float4 pa[2], pb[2];

    // Stage k-tile 0 into buffer 0
    #pragma unroll
    for (int i = 0; i < 2; i++) {
        pa[i] = *reinterpret_cast<const float4*>(&A[(size_t)(bm + arow[i]) * K + aq[i] * 4]);
        pb[i] = *reinterpret_cast<const float4*>(&B[(size_t)brow[i] * N + bn + bq[i] * 4]);
    }
    #pragma unroll
    for (int i = 0; i < 2; i++) {
        float4 v = pa[i];
        if (scale) {
            float dd = scale_of(scale, bm + arow[i], aq[i] * 4);
            v.x *= dd; v.y *= dd; v.z *= dd; v.w *= dd;
        }
        *reinterpret_cast<float4*>(&As[arow[i] * ASTR + aq[i] * 4]) = tf4(v);
        *reinterpret_cast<float4*>(&Bs[brow[i] * BSTR + bq[i] * 4]) = tf4(pb[i]);
    }
    __syncthreads();

    const int KT = K / GBK;
    for (int kt = 0; kt < KT; kt++) {
        const int b = kt & 1;
        const float* Asb = &As[b * ASZ];
        const float* Bsb = &Bs[b * BSZ];
        const int k0n = (kt + 1) * GBK;

        if (kt + 1 < KT) {
            #pragma unroll
            for (int i = 0; i < 2; i++) {
                pa[i] = *reinterpret_cast<const float4*>(&A[(size_t)(bm + arow[i]) * K + k0n + aq[i] * 4]);
                pb[i] = *reinterpret_cast<const float4*>(&B[(size_t)(k0n + brow[i]) * N + bn + bq[i] * 4]);
            }
        }

        #pragma unroll
        for (int kk = 0; kk < 2; kk++) {
            const int kb = kk * 8;
            uint32_t af[2][4], bf[8][2];
            #pragma unroll
            for (int mt = 0; mt < 2; mt++) {
                int rb = wm * 32 + mt * 16;
                af[mt][0] = __float_as_uint(Asb[(rb + r) * ASTR + kb + cq]);
                af[mt][1] = __float_as_uint(Asb[(rb + 8 + r) * ASTR + kb + cq]);
                af[mt][2] = __float_as_uint(Asb[(rb + r) * ASTR + kb + 4 + cq]);
                af[mt][3] = __float_as_uint(Asb[(rb + 8 + r) * ASTR + kb + 4 + cq]);
            }
            #pragma unroll
            for (int nt = 0; nt < 8; nt++) {
                int cb = wn * 64 + nt * 8 + r;
                bf[nt][0] = __float_as_uint(Bsb[(kb + cq) * BSTR + cb]);
                bf[nt][1] = __float_as_uint(Bsb[(kb + 4 + cq) * BSTR + cb]);
            }
            #pragma unroll
            for (int mt = 0; mt < 2; mt++)
                #pragma unroll
                for (int nt = 0; nt < 8; nt++)
                    mma_tf32(acc[mt][nt], af[mt], bf[nt]);
        }

        if (kt + 1 < KT) {
            float* Asn = &As[(1 - b) * ASZ];
            float* Bsn = &Bs[(1 - b) * BSZ];
            #pragma unroll
            for (int i = 0; i < 2; i++) {
                float4 v = pa[i];
                if (scale) {
                    float dd = scale_of(scale, bm + arow[i], k0n + aq[i] * 4);
                    v.x *= dd; v.y *= dd; v.z *= dd; v.w *= dd;
                }
                *reinterpret_cast<float4*>(&Asn[arow[i] * ASTR + aq[i] * 4]) = tf4(v);
                *reinterpret_cast<float4*>(&Bsn[brow[i] * BSTR + bq[i] * 4]) = tf4(pb[i]);
            }
        }
        __syncthreads();
    }

    // Epilogue with bias
    #pragma unroll
    for (int mt = 0; mt < 2; mt++) {
        int row0 = bm + wm * 32 + mt * 16 + r;
        #pragma unroll
        for (int nt = 0; nt < 8; nt++) {
            int col = bn + wn * 64 + nt * 8 + cq * 2;
            float b0 = bias[col], b1 = bias[col + 1];
            float2 v0 = make_float2(acc[mt][nt][0] + b0, acc[mt][nt][1] + b1);
            float2 v1 = make_float2(acc[mt][nt][2] + b0, acc[mt][nt][3] + b1);
            *reinterpret_cast<float2*>(&C[(size_t)row0 * N + col]) = v0;
            *reinterpret_cast<float2*>(&C[(size_t)(row0 + 8) * N + col]) = v1;
        }
    }
}

// Fused Q/K/V projection: blockIdx.z selects weight/bias/output.
__global__ __launch_bounds__(256, 2) void gemm_qkv(
    const float* __restrict__ X,
    const float* __restrict__ Wq, const float* __restrict__ Wk, const float* __restrict__ Wv,
    const float* __restrict__ bq, const float* __restrict__ bk, const float* __restrict__ bv,
    float* __restrict__ Q, float* __restrict__ K, float* __restrict__ V)
{
    const int z = blockIdx.z;
    const float* B    = (z == 0) ? Wq : (z == 1) ? Wk : Wv;
    const float* bias = (z == 0) ? bq : (z == 1) ? bk : bv;
    float*       C    = (z == 0) ? Q  : (z == 1) ? K  : V;
    gemm_body(X, B, bias, C, nullptr, HID, EE,
              blockIdx.y * GBM, blockIdx.x * GBN);
}

// O projection with fused diag scaling of A (=V).
__global__ __launch_bounds__(256, 2) void gemm_o(
    const float* __restrict__ V, const float* __restrict__ Wo,
    const float* __restrict__ bo, float* __restrict__ C,
    const float* __restrict__ diag)
{
    gemm_body(V, Wo, bo, C, diag, HID, HID,
              blockIdx.y * GBM, blockIdx.x * GBN);
}

// ---------------------------------------------------------------------------
// Score kernel with K-tile residency. Block (cb, rbg, p):
//   K[cb] tile stays in smem; loop over 4 Q row-blocks rb = rbg*4 + it:
//   S = Q[rb] @ K[cb]^T (128x128x64 tf32 mma), e = exp(S/1024),
//   column partial sums accumulated in REGISTERS across the 4 row-blocks,
//   diag captured when rb==cb. One smem reduce + one partG write per block.
// 8 warps (4a x 2b), warp tile 32(a) x 64(b). R8 fragment layout (SSTR 68).
// ---------------------------------------------------------------------------
#define SSTR 68

__global__ __launch_bounds__(256, 2) void score_diag_tc(
    const float* __restrict__ Q, const float* __restrict__ Km,
    float* __restrict__ diagE, float* __restrict__ partG)
{
    extern __shared__ float sm[];
    float* Ks   = sm;                   // 128 x SSTR
    float* Qs   = sm + 128 * SSTR;      // 128 x SSTR
    float* csum = sm + 2 * 128 * SSTR;  // 128

    const int t    = threadIdx.x;
    const int lane = t & 31, wid = t >> 5;
    const int wm = wid & 3, wn = wid >> 2;
    const int r = lane >> 2, cq = lane & 3;

    const int cb  = blockIdx.x;         // column block 0..15
    const int rbg = blockIdx.y;         // row-block group 0..3
    const int p   = blockIdx.z;         // pair 0..63
    const int bn  = cb * 128;
    const float* Qh = Q  + (size_t)p * LL * DH;
    const float* Kh = Km + (size_t)p * LL * DH;

    // Load K tile (cols) once, tf32-rounded
    #pragma unroll
    for (int i = 0; i < 8; i++) {
        int idx = t + i * 256;
        int row = idx >> 4, q = idx & 15;
        float4 v = *reinterpret_cast<const float4*>(&Kh[(size_t)(bn + row) * DH + q * 4]);
        *reinterpret_cast<float4*>(&Ks[row * SSTR + q * 4]) = tf4(v);
    }

    const float S = 1.0f / 1024.0f;
    float partial[8][2];
    #pragma unroll
    for (int nt = 0; nt < 8; nt++) { partial[nt][0] = 0.f; partial[nt][1] = 0.f; }

    for (int it = 0; it < RPG; it++) {
        const int rb = rbg * RPG + it;
        const int a0 = rb * 128;

        if (it > 0) __syncthreads();    // previous Qs consumers done
        #pragma unroll
        for (int i = 0; i < 8; i++) {
            int idx = t + i * 256;
            int row = idx >> 4, q = idx & 15;
            float4 v = *reinterpret_cast<const float4*>(&Qh[(size_t)(a0 + row) * DH + q * 4]);
            *reinterpret_cast<float4*>(&Qs[row * SSTR + q * 4]) = tf4(v);
        }
        __syncthreads();

        float acc[2][8][4];
        #pragma unroll
        for (int mt = 0; mt < 2; mt++)
            #pragma unroll
            for (int nt = 0; nt < 8; nt++)
                #pragma unroll
                for (int j = 0; j < 4; j++) acc[mt][nt][j] = 0.f;

        #pragma unroll
        for (int kk = 0; kk < 8; kk++) {
            const int kb = kk * 8;
            uint32_t af[2][4], bf[8][2];
            #pragma unroll
            for (int mt = 0; mt < 2; mt++) {
                int rbm = wm * 32 + mt * 16;
                af[mt][0] = __float_as_uint(Qs[(rbm + r) * SSTR + kb + cq]);
                af[mt][1] = __float_as_uint(Qs[(rbm + 8 + r) * SSTR + kb + cq]);
                af[mt][2] = __float_as_uint(Qs[(rbm + r) * SSTR + kb + 4 + cq]);
                af[mt][3] = __float_as_uint(Qs[(rbm + 8 + r) * SSTR + kb + 4 + cq]);
            }
            #pragma unroll
            for (int nt = 0; nt < 8; nt++) {
                int cbi = wn * 64 + nt * 8 + r;
                bf[nt][0] = __float_as_uint(Ks[cbi * SSTR + kb + cq]);
                bf[nt][1] = __float_as_uint(Ks[cbi * SSTR + kb + 4 + cq]);
            }
            #pragma unroll
            for (int mt = 0; mt < 2; mt++)
                #pragma unroll
                for (int nt = 0; nt < 8; nt++)
                    mma_tf32(acc[mt][nt], af[mt], bf[nt]);
        }

        // exp + per-warp column partials; capture diagonal when rb==cb
        const bool diagblk = (rb == cb);
        #pragma unroll
        for (int mt = 0; mt < 2; mt++) {
            int arow0 = wm * 32 + mt * 16 + r;
            #pragma unroll
            for (int nt = 0; nt < 8; nt++) {
                #pragma unroll
                for (int j = 0; j < 2; j++) {
                    int bcol = wn * 64 + nt * 8 + cq * 2 + j;
                    float e0 = __expf(acc[mt][nt][j] * S);
                    float e1 = __expf(acc[mt][nt][2 + j] * S);
                    partial[nt][j] += e0 + e1;
                    if (diagblk) {
                        if (arow0 == bcol)     diagE[(size_t)p * LL + bn + bcol] = e0;
                        if (arow0 + 8 == bcol) diagE[(size_t)p * LL + bn + bcol] = e1;
                    }
                }
            }
        }
    }

    // Reduce partials over the 8 row-groups within the warp
    #pragma unroll
    for (int nt = 0; nt < 8; nt++)
        #pragma unroll
        for (int j = 0; j < 2; j++) {
            float v = partial[nt][j];
            v += __shfl_xor_sync(0xFFFFFFFF, v, 4);
            v += __shfl_xor_sync(0xFFFFFFFF, v, 8);
            v += __shfl_xor_sync(0xFFFFFFFF, v, 16);
            partial[nt][j] = v;
        }

    __syncthreads();                    // Qs consumers done; csum safe to init
    if (t < 128) csum[t] = 0.f;
    __syncthreads();
    if (r == 0) {
        #pragma unroll
        for (int nt = 0; nt < 8; nt++)
            #pragma unroll
            for (int j = 0; j < 2; j++)
                atomicAdd(&csum[wn * 64 + nt * 8 + cq * 2 + j], partial[nt][j]);
    }
    __syncthreads();
    if (t < 128)
        partG[((size_t)rbg * NPAIR + p) * LL + bn + t] = csum[t];
}

// ---------------------------------------------------------------------------
// diag[p][c] = diagE[p][c] / sum_rbg part[rbg][p][c]
// ---------------------------------------------------------------------------
__global__ __launch_bounds__(256) void divide_kernel(
    const float* __restrict__ diagE, const float* __restrict__ part,
    float* __restrict__ diag)
{
    int i = blockIdx.x * 256 + threadIdx.x;           // over NPAIR*LL
    if (i >= NPAIR * LL) return;
    float s = 0.f;
    #pragma unroll
    for (int rb = 0; rb < RBG; rb++)
        s += part[(size_t)rb * NPAIR * LL + i];
    diag[i] = diagE[i] / s;
}

// ---------------------------------------------------------------------------
extern "C" void kernel_launch(void* const* d_in, const int* in_sizes, int n_in,
                              void* d_out, int out_size)
{
    const float* X  = (const float*)d_in[0];
    const float* Wq = (const float*)d_in[1];
    const float* bq = (const float*)d_in[2];
    const float* Wk = (const float*)d_in[3];
    const float* bk = (const float*)d_in[4];
    const float* Wv = (const float*)d_in[5];
    const float* bv = (const float*)d_in[6];
    const float* Wo = (const float*)d_in[7];
    const float* bo = (const float*)d_in[8];
    float* out = (float*)d_out;

    float *Q, *K, *V, *dgE, *pt, *dg;
    cudaGetSymbolAddress((void**)&Q,   g_Q);
    cudaGetSymbolAddress((void**)&K,   g_K);
    cudaGetSymbolAddress((void**)&V,   g_V);
    cudaGetSymbolAddress((void**)&dgE, g_diagE);
    cudaGetSymbolAddress((void**)&pt,  g_part);
    cudaGetSymbolAddress((void**)&dg,  g_diag);

    const int score_smem = (2 * 128 * SSTR + 128) * sizeof(float);
    static int attr_done = 0;
    if (!attr_done) {
        cudaFuncSetAttribute(score_diag_tc,
                             cudaFuncAttributeMaxDynamicSharedMemorySize, score_smem);
        attr_done = 1;
    }

    dim3 qkv_grid(HID / GBN, MROWS / GBM, 3);   // (8, 64, 3) = 1536 blocks
    gemm_qkv<<<qkv_grid, 256>>>(X, Wq, Wk, Wv, bq, bk, bv, Q, K, V);

    dim3 sgrid(LL / 128, RBG, NPAIR);           // (16, 4, 64) = 4096 blocks
    score_diag_tc<<<sgrid, 256, score_smem>>>(Q, K, dgE, pt);

    divide_kernel<<<(NPAIR * LL + 255) / 256, 256>>>(dgE, pt, dg);

    dim3 ogrid(HID / GBN, MROWS / GBM);         // (8, 64)
    gemm_o<<<ogrid, 256>>>(V, Wo, bo, out, dg);
}